// round 13
// baseline (speedup 1.0000x reference)
#include <cuda_runtime.h>
#include <cuda_fp16.h>
#include <cstdint>

#define SZ    4096
#define MTOT  8192
#define BM    128
#define BN    128
#define BK    64
#define KIT   (SZ / BK)          // 64 k-steps
#define NTHR  128                // 4 warps: 2m x 2n, warp tile 64x64
#define NSTGB 3                  // B cp.async stages
#define NSTGA 2                  // A fp16 ring slots (CTA-produced)

// device scratch (no allocation allowed in kernel_launch)
__device__ __half g_Gt[(size_t)SZ * SZ];     // Gt[n][k] = G[k][n], fp16, K-major

// ---------------------------------------------------------------------------
// helpers (base-PTX only: cp.async / ldmatrix / mma.sync)
// ---------------------------------------------------------------------------
__device__ __forceinline__ uint32_t smem_u32(const void* p) {
    uint32_t a;
    asm("{ .reg .u64 t; cvta.to.shared.u64 t, %1; cvt.u32.u64 %0, t; }"
        : "=r"(a) : "l"(p));
    return a;
}
__device__ __forceinline__ uint32_t swz128(uint32_t off) {
    return off ^ ((off >> 3) & 0x70);        // SW128: conflict-free 128B-row tiles
}
__device__ __forceinline__ void cp16(uint32_t sdst, const void* gsrc) {
    asm volatile("cp.async.cg.shared.global [%0], [%1], 16;" :: "r"(sdst), "l"(gsrc));
}
__device__ __forceinline__ void ldsm_x4(uint32_t& r0, uint32_t& r1, uint32_t& r2,
                                        uint32_t& r3, uint32_t addr) {
    asm volatile("ldmatrix.sync.aligned.m8n8.x4.shared.b16 {%0,%1,%2,%3}, [%4];"
                 : "=r"(r0), "=r"(r1), "=r"(r2), "=r"(r3) : "r"(addr));
}
__device__ __forceinline__ void mma16816(float* c, uint32_t a0, uint32_t a1,
                                         uint32_t a2, uint32_t a3,
                                         uint32_t b0, uint32_t b1) {
    asm volatile(
        "mma.sync.aligned.m16n8k16.row.col.f32.f16.f16.f32 "
        "{%0,%1,%2,%3}, {%4,%5,%6,%7}, {%8,%9}, {%0,%1,%2,%3};"
        : "+f"(c[0]), "+f"(c[1]), "+f"(c[2]), "+f"(c[3])
        : "r"(a0), "r"(a1), "r"(a2), "r"(a3), "r"(b0), "r"(b1));
}
// store 4 halves (2 x b32) as one 8-byte STS
__device__ __forceinline__ void sts64(uint32_t addr, uint32_t lo, uint32_t hi) {
    asm volatile("st.shared.v2.b32 [%0], {%1, %2};" :: "r"(addr), "r"(lo), "r"(hi));
}

// ---------------------------------------------------------------------------
// Kernel 1: build Gt[n][k] = G[k][n] in fp16.
// ---------------------------------------------------------------------------
__global__ void __launch_bounds__(256)
k_build_gt(const float* __restrict__ core0, const float* __restrict__ core1,
           const float* __restrict__ core2) {
    const int x1 = blockIdx.y;
    const int k  = blockIdx.x * 256 + threadIdx.x;

    float c1r[64];  // C1[k, x1, c, b]
    const float4* c1p = reinterpret_cast<const float4*>(core1 + ((size_t)k * 16 + x1) * 64);
#pragma unroll
    for (int i = 0; i < 16; i++) {
        float4 v = c1p[i];
        c1r[4 * i] = v.x; c1r[4 * i + 1] = v.y; c1r[4 * i + 2] = v.z; c1r[4 * i + 3] = v.w;
    }
#pragma unroll
    for (int yc = 0; yc < 4; yc++) {
        float M[4][8];
#pragma unroll
        for (int yy = 0; yy < 4; yy++) {
            const int y = yc * 4 + yy;
            const float4* gp = reinterpret_cast<const float4*>(core0 + ((size_t)k * 16 + y) * 8);
            float4 a = gp[0], b = gp[1];
            float g0[8] = {a.x, a.y, a.z, a.w, b.x, b.y, b.z, b.w};
#pragma unroll
            for (int c = 0; c < 8; c++) {
                float s = 0.f;
#pragma unroll
                for (int bb = 0; bb < 8; bb++) s = fmaf(c1r[c * 8 + bb], g0[bb], s);
                M[yy][c] = s;
            }
        }
#pragma unroll
        for (int x2 = 0; x2 < 16; x2++) {
            const float4* cp = reinterpret_cast<const float4*>(core2 + ((size_t)k * 16 + x2) * 8);
            float4 a = cp[0], b = cp[1];
            float c2v[8] = {a.x, a.y, a.z, a.w, b.x, b.y, b.z, b.w};
#pragma unroll
            for (int yy = 0; yy < 4; yy++) {
                float s = 0.f;
#pragma unroll
                for (int c = 0; c < 8; c++) s = fmaf(c2v[c], M[yy][c], s);
                const int n = (yc * 4 + yy) * 256 + x1 * 16 + x2;
                g_Gt[(size_t)n * SZ + k] = __float2half_rn(s);
            }
        }
    }
}

// ---------------------------------------------------------------------------
// Kernel 2: GEMM out[m][n] = sum_k x[m][k] * Gt[n][k] + bias[n]
// R10 shell (2 CTAs/SM, 4 warps 2m x 2n, 64x64 tiles), but A is read as fp32
// DIRECTLY from x via LDG.128 inside each k16 burst (latency hidden by the
// 32-MMA stream), converted to fp16 and STS'd into a 2-slot A ring.
// This deletes the 31us standalone convert kernel and the g_Xh roundtrip.
// ---------------------------------------------------------------------------
#define A_BYTES  (BM * BK * 2)                    // 16384 per A slot (fp16)
#define B_BYTES  (BN * BK * 2)                    // 16384 per B stage
#define SM_A     0
#define SM_B     (NSTGA * A_BYTES)                // 32768
#define SM_BIAS  (SM_B + NSTGB * B_BYTES)         // 81920
#define SM_TOTAL (SM_BIAS + BN * 4)               // 82432 (x2 CTAs = 161KB)

__global__ void __launch_bounds__(NTHR, 2)
k_gemm(const float* __restrict__ x, const float* __restrict__ bias,
       float* __restrict__ out) {
    extern __shared__ char smem[];
    const uint32_t sb = smem_u32(smem);
    const int tid  = threadIdx.x;
    const int lane = tid & 31;
    const int wid  = tid >> 5;
    const int wm   = wid & 1;            // 2 m-warps x 64 rows
    const int wn   = wid >> 1;           // 2 n-warps x 64 cols
    const int m0 = blockIdx.y * BM;
    const int n0 = blockIdx.x * BN;

    float* sbias = reinterpret_cast<float*>(smem + SM_BIAS);
    sbias[tid] = bias[n0 + tid];

    // ---- B loader: one B k-stage via cp.async (unchanged from R10) ----
    const int chunk = tid & 7;           // 16B chunk within 128B row
    const int rbase = tid >> 3;          // 0..15
    auto load_B = [&](int ks, int stage) {
        const uint32_t bb = sb + SM_B + stage * B_BYTES;
        const __half* bg = g_Gt + (size_t)(n0 + rbase) * SZ + ks * BK + chunk * 8;
#pragma unroll
        for (int it = 0; it < 8; it++) {
            const int r = rbase + 16 * it;
            cp16(bb + swz128((uint32_t)(r * 128 + chunk * 16)), bg + (size_t)(16 * it) * SZ);
        }
        asm volatile("cp.async.commit_group;" ::: "memory");
    };

    // ---- A fp32->fp16 producer: one k16 quarter of k-step ksn into slot ----
    // thread t: rows rw+32i (rw = t>>2), 16B chunk c = t&3 within the 64B
    // fp32 quarter. Converts float4 -> 2x half2 -> one STS.64.
    const int ac = tid & 3;
    const int arw = tid >> 2;            // 0..31
    auto conv_A_quarter = [&](int ksn, int q, int slot) {
        const uint32_t ab = sb + SM_A + slot * A_BYTES;
        const float* gp = x + (size_t)(m0 + arw) * SZ + ksn * BK + q * 16 + ac * 4;
        float4 f[4];
#pragma unroll
        for (int i = 0; i < 4; i++)
            f[i] = *reinterpret_cast<const float4*>(gp + (size_t)(32 * i) * SZ);
#pragma unroll
        for (int i = 0; i < 4; i++) {
            __half2 h0 = __floats2half2_rn(f[i].x, f[i].y);
            __half2 h1 = __floats2half2_rn(f[i].z, f[i].w);
            const int row = arw + 32 * i;
            sts64(ab + swz128((uint32_t)(row * 128 + q * 32 + ac * 8)),
                  *reinterpret_cast<uint32_t*>(&h0), *reinterpret_cast<uint32_t*>(&h1));
        }
    };

    float acc[4][8][4];
#pragma unroll
    for (int mt = 0; mt < 4; mt++)
#pragma unroll
        for (int nt = 0; nt < 8; nt++)
#pragma unroll
            for (int j = 0; j < 4; j++) acc[mt][nt][j] = 0.f;

    // prologue: A(0) -> slot 0 (blocking), B(0), B(1) in flight
    load_B(0, 0);
    load_B(1, 1);
#pragma unroll
    for (int q = 0; q < 4; q++) conv_A_quarter(0, q, 0);

    // lane pieces for ldmatrix addressing
    const int g = lane >> 3;                                   // 0..3
    const int arow_off = ((lane >> 3) & 1) * 8 + (lane & 7);   // A row within 16
    const int acol_off = (lane >> 4) << 4;                     // A col byte (0/16)
    const int brow_off = ((g & 2) << 2) + (lane & 7);          // B row within 16
    const int bcol_off = (g & 1) << 4;                         // B col byte (0/16)

    for (int ks = 0; ks < KIT; ks++) {
        asm volatile("cp.async.wait_group 1;" ::: "memory");
        __syncthreads();                 // B(ks) ready; A slot ks%2 visible
        if (ks + 2 < KIT) load_B(ks + 2, (ks + 2) % NSTGB);
        else              asm volatile("cp.async.commit_group;" ::: "memory");

        const uint32_t ab = sb + SM_A + (ks % NSTGA) * A_BYTES;
        const uint32_t bb = sb + SM_B + (ks % NSTGB) * B_BYTES;
        const int ksn = (ks + 1 < KIT) ? ks + 1 : 0;   // dummy-safe prefetch
        const int nslot = (ks + 1) % NSTGA;

#pragma unroll
        for (int k16 = 0; k16 < 4; k16++) {
            // issue next-kstep A LDGs first: latency covered by this MMA burst
            const float* gp = x + (size_t)(m0 + arw) * SZ + ksn * BK + k16 * 16 + ac * 4;
            float4 f[4];
#pragma unroll
            for (int i = 0; i < 4; i++)
                f[i] = *reinterpret_cast<const float4*>(gp + (size_t)(32 * i) * SZ);

            uint32_t a[4][4];
#pragma unroll
            for (int mt = 0; mt < 4; mt++) {
                const int row = wm * 64 + mt * 16 + arow_off;
                const int colb = k16 * 32 + acol_off;
                ldsm_x4(a[mt][0], a[mt][1], a[mt][2], a[mt][3],
                        ab + swz128((uint32_t)(row * 128 + colb)));
            }
            uint32_t b[8][2];
#pragma unroll
            for (int np = 0; np < 4; np++) {
                const int row = wn * 64 + np * 16 + brow_off;
                const int colb = k16 * 32 + bcol_off;
                uint32_t r0, r1, r2, r3;
                ldsm_x4(r0, r1, r2, r3, bb + swz128((uint32_t)(row * 128 + colb)));
                b[2 * np][0] = r0; b[2 * np][1] = r1;
                b[2 * np + 1][0] = r2; b[2 * np + 1][1] = r3;
            }
#pragma unroll
            for (int mt = 0; mt < 4; mt++)
#pragma unroll
                for (int nt = 0; nt < 8; nt++)
                    mma16816(acc[mt][nt], a[mt][0], a[mt][1], a[mt][2], a[mt][3],
                             b[nt][0], b[nt][1]);

            // convert + store the prefetched A quarter into the next slot
#pragma unroll
            for (int i = 0; i < 4; i++) {
                __half2 h0 = __floats2half2_rn(f[i].x, f[i].y);
                __half2 h1 = __floats2half2_rn(f[i].z, f[i].w);
                const int row = arw + 32 * i;
                sts64(sb + SM_A + nslot * A_BYTES +
                          swz128((uint32_t)(row * 128 + k16 * 32 + ac * 8)),
                      *reinterpret_cast<uint32_t*>(&h0),
                      *reinterpret_cast<uint32_t*>(&h1));
            }
        }
    }

    // ---- epilogue ----
    const int crow = lane >> 2;
    const int ccol = (lane & 3) * 2;
#pragma unroll
    for (int mt = 0; mt < 4; mt++) {
        const int m = m0 + wm * 64 + mt * 16 + crow;
#pragma unroll
        for (int nt = 0; nt < 8; nt++) {
            const int nc = wn * 64 + nt * 8 + ccol;
            float2 v0, v1;
            v0.x = acc[mt][nt][0] + sbias[nc];
            v0.y = acc[mt][nt][1] + sbias[nc + 1];
            v1.x = acc[mt][nt][2] + sbias[nc];
            v1.y = acc[mt][nt][3] + sbias[nc + 1];
            *reinterpret_cast<float2*>(out + (size_t)m * SZ + n0 + nc)       = v0;
            *reinterpret_cast<float2*>(out + (size_t)(m + 8) * SZ + n0 + nc) = v1;
        }
    }
}

// ---------------------------------------------------------------------------
extern "C" void kernel_launch(void* const* d_in, const int* in_sizes, int n_in,
                              void* d_out, int out_size) {
    const float* x     = (const float*)d_in[0];
    const float* core0 = (const float*)d_in[1];
    const float* core1 = (const float*)d_in[2];
    const float* core2 = (const float*)d_in[3];
    const float* bias  = (const float*)d_in[4];
    float* out = (float*)d_out;

    static bool attr_set = false;
    if (!attr_set) {
        cudaFuncSetAttribute(k_gemm, cudaFuncAttributeMaxDynamicSharedMemorySize, SM_TOTAL);
        attr_set = true;
    }

    k_build_gt<<<dim3(16, 16), 256>>>(core0, core1, core2);
    k_gemm<<<dim3(SZ / BN, MTOT / BM), NTHR, SM_TOTAL>>>(x, bias, out);
}

// round 14
// speedup vs baseline: 1.4582x; 1.4582x over previous
#include <cuda_runtime.h>
#include <cuda_fp16.h>
#include <cstdint>

#define SZ    4096
#define MTOT  8192
#define BM    128
#define BN    128
#define BK    64
#define KIT   (SZ / BK)          // 64 k-steps
#define NTHR  128                // 4 warps: 2m x 2n, warp tile 64x64
#define NSTG  3                  // cp.async stages (96KB -> 2 CTAs/SM)

// device scratch (no allocation allowed in kernel_launch)
__device__ __half g_Xh[(size_t)MTOT * SZ];   // x in fp16, row-major [M][K]
__device__ __half g_Gt[(size_t)SZ * SZ];     // Gt[n][k] = G[k][n], fp16, K-major

// ---------------------------------------------------------------------------
// helpers (base-PTX only: cp.async / ldmatrix / mma.sync)
// ---------------------------------------------------------------------------
__device__ __forceinline__ uint32_t smem_u32(const void* p) {
    uint32_t a;
    asm("{ .reg .u64 t; cvta.to.shared.u64 t, %1; cvt.u32.u64 %0, t; }"
        : "=r"(a) : "l"(p));
    return a;
}
__device__ __forceinline__ uint32_t swz128(uint32_t off) {
    return off ^ ((off >> 3) & 0x70);        // SW128: conflict-free 128B-row tiles
}
__device__ __forceinline__ void cp16(uint32_t sdst, const void* gsrc) {
    asm volatile("cp.async.cg.shared.global [%0], [%1], 16;" :: "r"(sdst), "l"(gsrc));
}
__device__ __forceinline__ void ldsm_x4(uint32_t& r0, uint32_t& r1, uint32_t& r2,
                                        uint32_t& r3, uint32_t addr) {
    asm volatile("ldmatrix.sync.aligned.m8n8.x4.shared.b16 {%0,%1,%2,%3}, [%4];"
                 : "=r"(r0), "=r"(r1), "=r"(r2), "=r"(r3) : "r"(addr));
}
__device__ __forceinline__ void mma16816(float* c, uint32_t a0, uint32_t a1,
                                         uint32_t a2, uint32_t a3,
                                         uint32_t b0, uint32_t b1) {
    asm volatile(
        "mma.sync.aligned.m16n8k16.row.col.f32.f16.f16.f32 "
        "{%0,%1,%2,%3}, {%4,%5,%6,%7}, {%8,%9}, {%0,%1,%2,%3};"
        : "+f"(c[0]), "+f"(c[1]), "+f"(c[2]), "+f"(c[3])
        : "r"(a0), "r"(a1), "r"(a2), "r"(a3), "r"(b0), "r"(b1));
}

// ---------------------------------------------------------------------------
// Kernel 1: x fp32 -> fp16 (separate: 16 regs, full occupancy)
// ---------------------------------------------------------------------------
__global__ void k_convert_x(const float4* __restrict__ x) {
    size_t i = (size_t)blockIdx.x * blockDim.x + threadIdx.x;   // over float4
    float4 v = x[i];
    __half2* o = reinterpret_cast<__half2*>(g_Xh) + 2 * i;
    o[0] = __floats2half2_rn(v.x, v.y);
    o[1] = __floats2half2_rn(v.z, v.w);
}

// ---------------------------------------------------------------------------
// Kernel 2: build Gt[n][k] = G[k][n] in fp16.
// ---------------------------------------------------------------------------
__global__ void __launch_bounds__(256)
k_build_gt(const float* __restrict__ core0, const float* __restrict__ core1,
           const float* __restrict__ core2) {
    const int x1 = blockIdx.y;
    const int k  = blockIdx.x * 256 + threadIdx.x;

    float c1r[64];  // C1[k, x1, c, b]
    const float4* c1p = reinterpret_cast<const float4*>(core1 + ((size_t)k * 16 + x1) * 64);
#pragma unroll
    for (int i = 0; i < 16; i++) {
        float4 v = c1p[i];
        c1r[4 * i] = v.x; c1r[4 * i + 1] = v.y; c1r[4 * i + 2] = v.z; c1r[4 * i + 3] = v.w;
    }
#pragma unroll
    for (int yc = 0; yc < 4; yc++) {
        float M[4][8];
#pragma unroll
        for (int yy = 0; yy < 4; yy++) {
            const int y = yc * 4 + yy;
            const float4* gp = reinterpret_cast<const float4*>(core0 + ((size_t)k * 16 + y) * 8);
            float4 a = gp[0], b = gp[1];
            float g0[8] = {a.x, a.y, a.z, a.w, b.x, b.y, b.z, b.w};
#pragma unroll
            for (int c = 0; c < 8; c++) {
                float s = 0.f;
#pragma unroll
                for (int bb = 0; bb < 8; bb++) s = fmaf(c1r[c * 8 + bb], g0[bb], s);
                M[yy][c] = s;
            }
        }
#pragma unroll
        for (int x2 = 0; x2 < 16; x2++) {
            const float4* cp = reinterpret_cast<const float4*>(core2 + ((size_t)k * 16 + x2) * 8);
            float4 a = cp[0], b = cp[1];
            float c2v[8] = {a.x, a.y, a.z, a.w, b.x, b.y, b.z, b.w};
#pragma unroll
            for (int yy = 0; yy < 4; yy++) {
                float s = 0.f;
#pragma unroll
                for (int c = 0; c < 8; c++) s = fmaf(c2v[c], M[yy][c], s);
                const int n = (yc * 4 + yy) * 256 + x1 * 16 + x2;
                g_Gt[(size_t)n * SZ + k] = __float2half_rn(s);
            }
        }
    }
}

// ---------------------------------------------------------------------------
// Kernel 3: GEMM out[m][n] = sum_k Xh[m][k] * Gt[n][k] + bias[n]
// R10 shell: 2 CTAs/SM, 4 warps (2m x 2n, 64x64), 3-stage cp.async.
// CHANGE vs R10: load_stage(ks+2) is issued AFTER k16=0's MMA burst, not
// before it — the 16 LDGSTS per warp (~256 issue-cyc/SMSP) previously held
// the issue port at the top of every k-step while the tensor pipe idled.
// ---------------------------------------------------------------------------
#define A_BYTES  (BM * BK * 2)                    // 16384 per stage
#define B_BYTES  (BN * BK * 2)                    // 16384 per stage
#define SM_A     0
#define SM_B     (NSTG * A_BYTES)                 // 49152
#define SM_BIAS  (SM_B + NSTG * B_BYTES)          // 98304
#define SM_TOTAL (SM_BIAS + BN * 4)               // 98816 (x2 CTAs = 193KB)

__global__ void __launch_bounds__(NTHR, 2)
k_gemm(const float* __restrict__ bias, float* __restrict__ out) {
    extern __shared__ char smem[];
    const uint32_t sb = smem_u32(smem);
    const int tid  = threadIdx.x;
    const int lane = tid & 31;
    const int wid  = tid >> 5;
    const int wm   = wid & 1;            // 2 m-warps x 64 rows
    const int wn   = wid >> 1;           // 2 n-warps x 64 cols
    const int m0 = blockIdx.y * BM;
    const int n0 = blockIdx.x * BN;

    float* sbias = reinterpret_cast<float*>(smem + SM_BIAS);
    sbias[tid] = bias[n0 + tid];

    // ---- loader: one full (A,B) k-stage; 128 threads, 16B per cp ----
    const int chunk = tid & 7;           // 16B chunk within 128B row
    const int rbase = tid >> 3;          // 0..15
    auto load_stage = [&](int ks, int stage) {
        const int k0 = ks * BK;
        const uint32_t ab = sb + SM_A + stage * A_BYTES;
        const uint32_t bb = sb + SM_B + stage * B_BYTES;
        const __half* ag = g_Xh + (size_t)(m0 + rbase) * SZ + k0 + chunk * 8;
        const __half* bg = g_Gt + (size_t)(n0 + rbase) * SZ + k0 + chunk * 8;
#pragma unroll
        for (int it = 0; it < 8; it++) {   // A: 128 rows
            const int r = rbase + 16 * it;
            cp16(ab + swz128((uint32_t)(r * 128 + chunk * 16)), ag + (size_t)(16 * it) * SZ);
        }
#pragma unroll
        for (int it = 0; it < 8; it++) {   // B: 128 rows
            const int r = rbase + 16 * it;
            cp16(bb + swz128((uint32_t)(r * 128 + chunk * 16)), bg + (size_t)(16 * it) * SZ);
        }
        asm volatile("cp.async.commit_group;" ::: "memory");
    };

    float acc[4][8][4];
#pragma unroll
    for (int mt = 0; mt < 4; mt++)
#pragma unroll
        for (int nt = 0; nt < 8; nt++)
#pragma unroll
            for (int j = 0; j < 4; j++) acc[mt][nt][j] = 0.f;

    load_stage(0, 0);
    load_stage(1, 1);

    // lane pieces for ldmatrix addressing
    const int g = lane >> 3;                                   // 0..3
    const int arow_off = ((lane >> 3) & 1) * 8 + (lane & 7);   // A row within 16
    const int acol_off = (lane >> 4) << 4;                     // A col byte (0/16)
    const int brow_off = ((g & 2) << 2) + (lane & 7);          // B row within 16
    const int bcol_off = (g & 1) << 4;                         // B col byte (0/16)

    // one k16 sub-step: frag loads + 32 MMAs (frags scoped locally: no reg growth)
    auto do_k16 = [&](uint32_t ab, uint32_t bb, int k16) {
        uint32_t a[4][4];
#pragma unroll
        for (int mt = 0; mt < 4; mt++) {
            const int row = wm * 64 + mt * 16 + arow_off;
            const int colb = k16 * 32 + acol_off;
            ldsm_x4(a[mt][0], a[mt][1], a[mt][2], a[mt][3],
                    ab + swz128((uint32_t)(row * 128 + colb)));
        }
        uint32_t b[8][2];
#pragma unroll
        for (int np = 0; np < 4; np++) {
            const int row = wn * 64 + np * 16 + brow_off;
            const int colb = k16 * 32 + bcol_off;
            uint32_t r0, r1, r2, r3;
            ldsm_x4(r0, r1, r2, r3, bb + swz128((uint32_t)(row * 128 + colb)));
            b[2 * np][0] = r0; b[2 * np][1] = r1;
            b[2 * np + 1][0] = r2; b[2 * np + 1][1] = r3;
        }
#pragma unroll
        for (int mt = 0; mt < 4; mt++)
#pragma unroll
            for (int nt = 0; nt < 8; nt++)
                mma16816(acc[mt][nt], a[mt][0], a[mt][1], a[mt][2], a[mt][3],
                         b[nt][0], b[nt][1]);
    };

    for (int ks = 0; ks < KIT; ks++) {
        asm volatile("cp.async.wait_group 1;" ::: "memory");
        __syncthreads();

        const uint32_t ab = sb + SM_A + (ks % NSTG) * A_BYTES;
        const uint32_t bb = sb + SM_B + (ks % NSTG) * B_BYTES;

        // start the tensor pipe FIRST...
        do_k16(ab, bb, 0);

        // ...then issue next-stage cp.async under the MMA shadow
        if (ks + 2 < KIT) load_stage(ks + 2, (ks + 2) % NSTG);
        else              asm volatile("cp.async.commit_group;" ::: "memory");

        do_k16(ab, bb, 1);
        do_k16(ab, bb, 2);
        do_k16(ab, bb, 3);
    }

    // ---- epilogue ----
    const int crow = lane >> 2;
    const int ccol = (lane & 3) * 2;
#pragma unroll
    for (int mt = 0; mt < 4; mt++) {
        const int m = m0 + wm * 64 + mt * 16 + crow;
#pragma unroll
        for (int nt = 0; nt < 8; nt++) {
            const int nc = wn * 64 + nt * 8 + ccol;
            float2 v0, v1;
            v0.x = acc[mt][nt][0] + sbias[nc];
            v0.y = acc[mt][nt][1] + sbias[nc + 1];
            v1.x = acc[mt][nt][2] + sbias[nc];
            v1.y = acc[mt][nt][3] + sbias[nc + 1];
            *reinterpret_cast<float2*>(out + (size_t)m * SZ + n0 + nc)       = v0;
            *reinterpret_cast<float2*>(out + (size_t)(m + 8) * SZ + n0 + nc) = v1;
        }
    }
}

// ---------------------------------------------------------------------------
extern "C" void kernel_launch(void* const* d_in, const int* in_sizes, int n_in,
                              void* d_out, int out_size) {
    const float* x     = (const float*)d_in[0];
    const float* core0 = (const float*)d_in[1];
    const float* core1 = (const float*)d_in[2];
    const float* core2 = (const float*)d_in[3];
    const float* bias  = (const float*)d_in[4];
    float* out = (float*)d_out;

    static bool attr_set = false;
    if (!attr_set) {
        cudaFuncSetAttribute(k_gemm, cudaFuncAttributeMaxDynamicSharedMemorySize, SM_TOTAL);
        attr_set = true;
    }

    k_convert_x<<<(int)((size_t)MTOT * SZ / 4 / 256), 256>>>(
        reinterpret_cast<const float4*>(x));
    k_build_gt<<<dim3(16, 16), 256>>>(core0, core1, core2);
    k_gemm<<<dim3(SZ / BN, MTOT / BM), NTHR, SM_TOTAL>>>(bias, out);
}

// round 15
// speedup vs baseline: 1.4860x; 1.0191x over previous
#include <cuda_runtime.h>
#include <cuda_fp16.h>
#include <cstdint>

#define SZ    4096
#define MTOT  8192
#define BM    128
#define BN    128
#define BK    64
#define KIT   (SZ / BK)          // 64 k-steps
#define NTHR  128                // 4 warps: 2m x 2n, warp tile 64x64
#define NSTG  3                  // cp.async stages (96KB -> 2 CTAs/SM)

// device scratch (no allocation allowed in kernel_launch)
__device__ __half g_Xh[(size_t)MTOT * SZ];   // x in fp16, row-major [M][K]
__device__ __half g_Gt[(size_t)SZ * SZ];     // Gt[n][k] = G[k][n], fp16, K-major

// ---------------------------------------------------------------------------
// helpers (base-PTX only: cp.async / ldmatrix / mma.sync)
// ---------------------------------------------------------------------------
__device__ __forceinline__ uint32_t smem_u32(const void* p) {
    uint32_t a;
    asm("{ .reg .u64 t; cvta.to.shared.u64 t, %1; cvt.u32.u64 %0, t; }"
        : "=r"(a) : "l"(p));
    return a;
}
__device__ __forceinline__ uint32_t swz128(uint32_t off) {
    return off ^ ((off >> 3) & 0x70);        // SW128: conflict-free 128B-row tiles
}
__device__ __forceinline__ void cp16(uint32_t sdst, const void* gsrc) {
    asm volatile("cp.async.cg.shared.global [%0], [%1], 16;" :: "r"(sdst), "l"(gsrc));
}
__device__ __forceinline__ void ldsm_x4(uint32_t& r0, uint32_t& r1, uint32_t& r2,
                                        uint32_t& r3, uint32_t addr) {
    asm volatile("ldmatrix.sync.aligned.m8n8.x4.shared.b16 {%0,%1,%2,%3}, [%4];"
                 : "=r"(r0), "=r"(r1), "=r"(r2), "=r"(r3) : "r"(addr));
}
__device__ __forceinline__ void mma16816(float* c, uint32_t a0, uint32_t a1,
                                         uint32_t a2, uint32_t a3,
                                         uint32_t b0, uint32_t b1) {
    asm volatile(
        "mma.sync.aligned.m16n8k16.row.col.f32.f16.f16.f32 "
        "{%0,%1,%2,%3}, {%4,%5,%6,%7}, {%8,%9}, {%0,%1,%2,%3};"
        : "+f"(c[0]), "+f"(c[1]), "+f"(c[2]), "+f"(c[3])
        : "r"(a0), "r"(a1), "r"(a2), "r"(a3), "r"(b0), "r"(b1));
}

// ---------------------------------------------------------------------------
// Kernel 1: x fp32 -> fp16 (separate: 16 regs, full occupancy)
// ---------------------------------------------------------------------------
__global__ void k_convert_x(const float4* __restrict__ x) {
    size_t i = (size_t)blockIdx.x * blockDim.x + threadIdx.x;   // over float4
    float4 v = x[i];
    __half2* o = reinterpret_cast<__half2*>(g_Xh) + 2 * i;
    o[0] = __floats2half2_rn(v.x, v.y);
    o[1] = __floats2half2_rn(v.z, v.w);
}

// ---------------------------------------------------------------------------
// Kernel 2: build Gt[n][k] = G[k][n] in fp16.
// ---------------------------------------------------------------------------
__global__ void __launch_bounds__(256)
k_build_gt(const float* __restrict__ core0, const float* __restrict__ core1,
           const float* __restrict__ core2) {
    const int x1 = blockIdx.y;
    const int k  = blockIdx.x * 256 + threadIdx.x;

    float c1r[64];  // C1[k, x1, c, b]
    const float4* c1p = reinterpret_cast<const float4*>(core1 + ((size_t)k * 16 + x1) * 64);
#pragma unroll
    for (int i = 0; i < 16; i++) {
        float4 v = c1p[i];
        c1r[4 * i] = v.x; c1r[4 * i + 1] = v.y; c1r[4 * i + 2] = v.z; c1r[4 * i + 3] = v.w;
    }
#pragma unroll
    for (int yc = 0; yc < 4; yc++) {
        float M[4][8];
#pragma unroll
        for (int yy = 0; yy < 4; yy++) {
            const int y = yc * 4 + yy;
            const float4* gp = reinterpret_cast<const float4*>(core0 + ((size_t)k * 16 + y) * 8);
            float4 a = gp[0], b = gp[1];
            float g0[8] = {a.x, a.y, a.z, a.w, b.x, b.y, b.z, b.w};
#pragma unroll
            for (int c = 0; c < 8; c++) {
                float s = 0.f;
#pragma unroll
                for (int bb = 0; bb < 8; bb++) s = fmaf(c1r[c * 8 + bb], g0[bb], s);
                M[yy][c] = s;
            }
        }
#pragma unroll
        for (int x2 = 0; x2 < 16; x2++) {
            const float4* cp = reinterpret_cast<const float4*>(core2 + ((size_t)k * 16 + x2) * 8);
            float4 a = cp[0], b = cp[1];
            float c2v[8] = {a.x, a.y, a.z, a.w, b.x, b.y, b.z, b.w};
#pragma unroll
            for (int yy = 0; yy < 4; yy++) {
                float s = 0.f;
#pragma unroll
                for (int c = 0; c < 8; c++) s = fmaf(c2v[c], M[yy][c], s);
                const int n = (yc * 4 + yy) * 256 + x1 * 16 + x2;
                g_Gt[(size_t)n * SZ + k] = __float2half_rn(s);
            }
        }
    }
}

// ---------------------------------------------------------------------------
// Kernel 3: GEMM out[m][n] = sum_k Xh[m][k] * Gt[n][k] + bias[n]
// R14 shell: 2 CTAs/SM, 4 warps (2m x 2n, 64x64), 3-stage cp.async with
// loads issued in the MMA shadow. CHANGE vs R14: the 16-cp burst is split —
// A-half (own commit group) after k16=0, B-half after k16=1 — halving the
// issue-port monopolization per shadow. wait_group 2 keeps the two newest
// groups (stage ks+2's A and B) outstanding; stage ks+1 is complete at the
// barrier, same prefetch distance as R14.
// ---------------------------------------------------------------------------
#define A_BYTES  (BM * BK * 2)                    // 16384 per stage
#define B_BYTES  (BN * BK * 2)                    // 16384 per stage
#define SM_A     0
#define SM_B     (NSTG * A_BYTES)                 // 49152
#define SM_BIAS  (SM_B + NSTG * B_BYTES)          // 98304
#define SM_TOTAL (SM_BIAS + BN * 4)               // 98816 (x2 CTAs = 193KB)

__global__ void __launch_bounds__(NTHR, 2)
k_gemm(const float* __restrict__ bias, float* __restrict__ out) {
    extern __shared__ char smem[];
    const uint32_t sb = smem_u32(smem);
    const int tid  = threadIdx.x;
    const int lane = tid & 31;
    const int wid  = tid >> 5;
    const int wm   = wid & 1;            // 2 m-warps x 64 rows
    const int wn   = wid >> 1;           // 2 n-warps x 64 cols
    const int m0 = blockIdx.y * BM;
    const int n0 = blockIdx.x * BN;

    float* sbias = reinterpret_cast<float*>(smem + SM_BIAS);
    sbias[tid] = bias[n0 + tid];

    // ---- loaders: A-half and B-half of one k-stage, separate commit groups ----
    const int chunk = tid & 7;           // 16B chunk within 128B row
    const int rbase = tid >> 3;          // 0..15
    auto load_A = [&](int ks, int stage) {
        const uint32_t ab = sb + SM_A + stage * A_BYTES;
        const __half* ag = g_Xh + (size_t)(m0 + rbase) * SZ + ks * BK + chunk * 8;
#pragma unroll
        for (int it = 0; it < 8; it++) {
            const int r = rbase + 16 * it;
            cp16(ab + swz128((uint32_t)(r * 128 + chunk * 16)), ag + (size_t)(16 * it) * SZ);
        }
        asm volatile("cp.async.commit_group;" ::: "memory");
    };
    auto load_B = [&](int ks, int stage) {
        const uint32_t bb = sb + SM_B + stage * B_BYTES;
        const __half* bg = g_Gt + (size_t)(n0 + rbase) * SZ + ks * BK + chunk * 8;
#pragma unroll
        for (int it = 0; it < 8; it++) {
            const int r = rbase + 16 * it;
            cp16(bb + swz128((uint32_t)(r * 128 + chunk * 16)), bg + (size_t)(16 * it) * SZ);
        }
        asm volatile("cp.async.commit_group;" ::: "memory");
    };

    float acc[4][8][4];
#pragma unroll
    for (int mt = 0; mt < 4; mt++)
#pragma unroll
        for (int nt = 0; nt < 8; nt++)
#pragma unroll
            for (int j = 0; j < 4; j++) acc[mt][nt][j] = 0.f;

    load_A(0, 0); load_B(0, 0);
    load_A(1, 1); load_B(1, 1);

    // lane pieces for ldmatrix addressing
    const int g = lane >> 3;                                   // 0..3
    const int arow_off = ((lane >> 3) & 1) * 8 + (lane & 7);   // A row within 16
    const int acol_off = (lane >> 4) << 4;                     // A col byte (0/16)
    const int brow_off = ((g & 2) << 2) + (lane & 7);          // B row within 16
    const int bcol_off = (g & 1) << 4;                         // B col byte (0/16)

    // one k16 sub-step: frag loads + 32 MMAs (frags scoped locally)
    auto do_k16 = [&](uint32_t ab, uint32_t bb, int k16) {
        uint32_t a[4][4];
#pragma unroll
        for (int mt = 0; mt < 4; mt++) {
            const int row = wm * 64 + mt * 16 + arow_off;
            const int colb = k16 * 32 + acol_off;
            ldsm_x4(a[mt][0], a[mt][1], a[mt][2], a[mt][3],
                    ab + swz128((uint32_t)(row * 128 + colb)));
        }
        uint32_t b[8][2];
#pragma unroll
        for (int np = 0; np < 4; np++) {
            const int row = wn * 64 + np * 16 + brow_off;
            const int colb = k16 * 32 + bcol_off;
            uint32_t r0, r1, r2, r3;
            ldsm_x4(r0, r1, r2, r3, bb + swz128((uint32_t)(row * 128 + colb)));
            b[2 * np][0] = r0; b[2 * np][1] = r1;
            b[2 * np + 1][0] = r2; b[2 * np + 1][1] = r3;
        }
#pragma unroll
        for (int mt = 0; mt < 4; mt++)
#pragma unroll
            for (int nt = 0; nt < 8; nt++)
                mma16816(acc[mt][nt], a[mt][0], a[mt][1], a[mt][2], a[mt][3],
                         b[nt][0], b[nt][1]);
    };

    for (int ks = 0; ks < KIT; ks++) {
        asm volatile("cp.async.wait_group 2;" ::: "memory");
        __syncthreads();

        const uint32_t ab = sb + SM_A + (ks % NSTG) * A_BYTES;
        const uint32_t bb = sb + SM_B + (ks % NSTG) * B_BYTES;
        const bool pf = (ks + 2 < KIT);

        do_k16(ab, bb, 0);
        if (pf) load_A(ks + 2, (ks + 2) % NSTG);
        else    asm volatile("cp.async.commit_group;" ::: "memory");

        do_k16(ab, bb, 1);
        if (pf) load_B(ks + 2, (ks + 2) % NSTG);
        else    asm volatile("cp.async.commit_group;" ::: "memory");

        do_k16(ab, bb, 2);
        do_k16(ab, bb, 3);
    }

    // ---- epilogue ----
    const int crow = lane >> 2;
    const int ccol = (lane & 3) * 2;
#pragma unroll
    for (int mt = 0; mt < 4; mt++) {
        const int m = m0 + wm * 64 + mt * 16 + crow;
#pragma unroll
        for (int nt = 0; nt < 8; nt++) {
            const int nc = wn * 64 + nt * 8 + ccol;
            float2 v0, v1;
            v0.x = acc[mt][nt][0] + sbias[nc];
            v0.y = acc[mt][nt][1] + sbias[nc + 1];
            v1.x = acc[mt][nt][2] + sbias[nc];
            v1.y = acc[mt][nt][3] + sbias[nc + 1];
            *reinterpret_cast<float2*>(out + (size_t)m * SZ + n0 + nc)       = v0;
            *reinterpret_cast<float2*>(out + (size_t)(m + 8) * SZ + n0 + nc) = v1;
        }
    }
}

// ---------------------------------------------------------------------------
extern "C" void kernel_launch(void* const* d_in, const int* in_sizes, int n_in,
                              void* d_out, int out_size) {
    const float* x     = (const float*)d_in[0];
    const float* core0 = (const float*)d_in[1];
    const float* core1 = (const float*)d_in[2];
    const float* core2 = (const float*)d_in[3];
    const float* bias  = (const float*)d_in[4];
    float* out = (float*)d_out;

    static bool attr_set = false;
    if (!attr_set) {
        cudaFuncSetAttribute(k_gemm, cudaFuncAttributeMaxDynamicSharedMemorySize, SM_TOTAL);
        attr_set = true;
    }

    k_convert_x<<<(int)((size_t)MTOT * SZ / 4 / 256), 256>>>(
        reinterpret_cast<const float4*>(x));
    k_build_gt<<<dim3(16, 16), 256>>>(core0, core1, core2);
    k_gemm<<<dim3(SZ / BN, MTOT / BM), NTHR, SM_TOTAL>>>(bias, out);
}

// round 16
// speedup vs baseline: 1.5398x; 1.0362x over previous
#include <cuda_runtime.h>
#include <cuda_fp16.h>
#include <cstdint>

#define SZ    4096
#define MTOT  8192
#define BM    128
#define BN    128
#define BK    64
#define KIT   (SZ / BK)          // 64 k-steps
#define NTHR  128                // 4 warps: 2m x 2n, warp tile 64x64
#define NSTG  3                  // cp.async stages (96KB -> 2 CTAs/SM)

// device scratch (no allocation allowed in kernel_launch)
__device__ __half g_Xh[(size_t)MTOT * SZ];   // x in fp16, row-major [M][K]
__device__ __half g_Gt[(size_t)SZ * SZ];     // Gt[n][k] = G[k][n], fp16, K-major

// ---------------------------------------------------------------------------
// helpers (base-PTX only: cp.async / ldmatrix / mma.sync)
// ---------------------------------------------------------------------------
__device__ __forceinline__ uint32_t smem_u32(const void* p) {
    uint32_t a;
    asm("{ .reg .u64 t; cvta.to.shared.u64 t, %1; cvt.u32.u64 %0, t; }"
        : "=r"(a) : "l"(p));
    return a;
}
__device__ __forceinline__ uint32_t swz128(uint32_t off) {
    return off ^ ((off >> 3) & 0x70);        // SW128: conflict-free 128B-row tiles
}
__device__ __forceinline__ void cp16(uint32_t sdst, const void* gsrc) {
    asm volatile("cp.async.cg.shared.global [%0], [%1], 16;" :: "r"(sdst), "l"(gsrc));
}
__device__ __forceinline__ void ldsm_x4(uint32_t& r0, uint32_t& r1, uint32_t& r2,
                                        uint32_t& r3, uint32_t addr) {
    asm volatile("ldmatrix.sync.aligned.m8n8.x4.shared.b16 {%0,%1,%2,%3}, [%4];"
                 : "=r"(r0), "=r"(r1), "=r"(r2), "=r"(r3) : "r"(addr));
}
__device__ __forceinline__ void mma16816(float* c, uint32_t a0, uint32_t a1,
                                         uint32_t a2, uint32_t a3,
                                         uint32_t b0, uint32_t b1) {
    asm volatile(
        "mma.sync.aligned.m16n8k16.row.col.f32.f16.f16.f32 "
        "{%0,%1,%2,%3}, {%4,%5,%6,%7}, {%8,%9}, {%0,%1,%2,%3};"
        : "+f"(c[0]), "+f"(c[1]), "+f"(c[2]), "+f"(c[3])
        : "r"(a0), "r"(a1), "r"(a2), "r"(a3), "r"(b0), "r"(b1));
}

// ---------------------------------------------------------------------------
// Kernel 1: x fp32 -> fp16 (separate: 16 regs, full occupancy)
// ---------------------------------------------------------------------------
__global__ void k_convert_x(const float4* __restrict__ x) {
    size_t i = (size_t)blockIdx.x * blockDim.x + threadIdx.x;   // over float4
    float4 v = x[i];
    __half2* o = reinterpret_cast<__half2*>(g_Xh) + 2 * i;
    o[0] = __floats2half2_rn(v.x, v.y);
    o[1] = __floats2half2_rn(v.z, v.w);
}

// ---------------------------------------------------------------------------
// Kernel 2: build Gt[n][k] = G[k][n] in fp16.
// ---------------------------------------------------------------------------
__global__ void __launch_bounds__(256)
k_build_gt(const float* __restrict__ core0, const float* __restrict__ core1,
           const float* __restrict__ core2) {
    const int x1 = blockIdx.y;
    const int k  = blockIdx.x * 256 + threadIdx.x;

    float c1r[64];  // C1[k, x1, c, b]
    const float4* c1p = reinterpret_cast<const float4*>(core1 + ((size_t)k * 16 + x1) * 64);
#pragma unroll
    for (int i = 0; i < 16; i++) {
        float4 v = c1p[i];
        c1r[4 * i] = v.x; c1r[4 * i + 1] = v.y; c1r[4 * i + 2] = v.z; c1r[4 * i + 3] = v.w;
    }
#pragma unroll
    for (int yc = 0; yc < 4; yc++) {
        float M[4][8];
#pragma unroll
        for (int yy = 0; yy < 4; yy++) {
            const int y = yc * 4 + yy;
            const float4* gp = reinterpret_cast<const float4*>(core0 + ((size_t)k * 16 + y) * 8);
            float4 a = gp[0], b = gp[1];
            float g0[8] = {a.x, a.y, a.z, a.w, b.x, b.y, b.z, b.w};
#pragma unroll
            for (int c = 0; c < 8; c++) {
                float s = 0.f;
#pragma unroll
                for (int bb = 0; bb < 8; bb++) s = fmaf(c1r[c * 8 + bb], g0[bb], s);
                M[yy][c] = s;
            }
        }
#pragma unroll
        for (int x2 = 0; x2 < 16; x2++) {
            const float4* cp = reinterpret_cast<const float4*>(core2 + ((size_t)k * 16 + x2) * 8);
            float4 a = cp[0], b = cp[1];
            float c2v[8] = {a.x, a.y, a.z, a.w, b.x, b.y, b.z, b.w};
#pragma unroll
            for (int yy = 0; yy < 4; yy++) {
                float s = 0.f;
#pragma unroll
                for (int c = 0; c < 8; c++) s = fmaf(c2v[c], M[yy][c], s);
                const int n = (yc * 4 + yy) * 256 + x1 * 16 + x2;
                g_Gt[(size_t)n * SZ + k] = __float2half_rn(s);
            }
        }
    }
}

// ---------------------------------------------------------------------------
// Kernel 3: GEMM out[m][n] = sum_k Xh[m][k] * Gt[n][k] + bias[n]
// R15 shell: 2 CTAs/SM, 4 warps (2m x 2n, 64x64), 3-stage cp.async, loads
// in the MMA shadow. CHANGE vs R15: bursts quartered — 4 cp.async after
// EACH k16 (A half 0 | A half 1 + commit | B half 0 | B half 1 + commit).
// Still exactly 2 commit groups per k-step; wait_group 2 distance unchanged.
// ---------------------------------------------------------------------------
#define A_BYTES  (BM * BK * 2)                    // 16384 per stage
#define B_BYTES  (BN * BK * 2)                    // 16384 per stage
#define SM_A     0
#define SM_B     (NSTG * A_BYTES)                 // 49152
#define SM_BIAS  (SM_B + NSTG * B_BYTES)          // 98304
#define SM_TOTAL (SM_BIAS + BN * 4)               // 98816 (x2 CTAs = 193KB)

__global__ void __launch_bounds__(NTHR, 2)
k_gemm(const float* __restrict__ bias, float* __restrict__ out) {
    extern __shared__ char smem[];
    const uint32_t sb = smem_u32(smem);
    const int tid  = threadIdx.x;
    const int lane = tid & 31;
    const int wid  = tid >> 5;
    const int wm   = wid & 1;            // 2 m-warps x 64 rows
    const int wn   = wid >> 1;           // 2 n-warps x 64 cols
    const int m0 = blockIdx.y * BM;
    const int n0 = blockIdx.x * BN;

    float* sbias = reinterpret_cast<float*>(smem + SM_BIAS);
    sbias[tid] = bias[n0 + tid];

    // ---- loaders: quarter-stage packets (4 cp.async each) ----
    const int chunk = tid & 7;           // 16B chunk within 128B row
    const int rbase = tid >> 3;          // 0..15
    // h = 0/1 selects rows [h*64, h*64+64) of the 128-row operand tile
    auto load_A_half = [&](int ks, int stage, int h) {
        const uint32_t ab = sb + SM_A + stage * A_BYTES;
        const __half* ag = g_Xh + (size_t)(m0 + rbase + 64 * h) * SZ + ks * BK + chunk * 8;
#pragma unroll
        for (int it = 0; it < 4; it++) {
            const int r = rbase + 64 * h + 16 * it;
            cp16(ab + swz128((uint32_t)(r * 128 + chunk * 16)), ag + (size_t)(16 * it) * SZ);
        }
    };
    auto load_B_half = [&](int ks, int stage, int h) {
        const uint32_t bb = sb + SM_B + stage * B_BYTES;
        const __half* bg = g_Gt + (size_t)(n0 + rbase + 64 * h) * SZ + ks * BK + chunk * 8;
#pragma unroll
        for (int it = 0; it < 4; it++) {
            const int r = rbase + 64 * h + 16 * it;
            cp16(bb + swz128((uint32_t)(r * 128 + chunk * 16)), bg + (size_t)(16 * it) * SZ);
        }
    };
    auto commit = [&]() {
        asm volatile("cp.async.commit_group;" ::: "memory");
    };

    float acc[4][8][4];
#pragma unroll
    for (int mt = 0; mt < 4; mt++)
#pragma unroll
        for (int nt = 0; nt < 8; nt++)
#pragma unroll
            for (int j = 0; j < 4; j++) acc[mt][nt][j] = 0.f;

    load_A_half(0, 0, 0); load_A_half(0, 0, 1); commit();
    load_B_half(0, 0, 0); load_B_half(0, 0, 1); commit();
    load_A_half(1, 1, 0); load_A_half(1, 1, 1); commit();
    load_B_half(1, 1, 0); load_B_half(1, 1, 1); commit();

    // lane pieces for ldmatrix addressing
    const int g = lane >> 3;                                   // 0..3
    const int arow_off = ((lane >> 3) & 1) * 8 + (lane & 7);   // A row within 16
    const int acol_off = (lane >> 4) << 4;                     // A col byte (0/16)
    const int brow_off = ((g & 2) << 2) + (lane & 7);          // B row within 16
    const int bcol_off = (g & 1) << 4;                         // B col byte (0/16)

    // one k16 sub-step: frag loads + 32 MMAs (frags scoped locally)
    auto do_k16 = [&](uint32_t ab, uint32_t bb, int k16) {
        uint32_t a[4][4];
#pragma unroll
        for (int mt = 0; mt < 4; mt++) {
            const int row = wm * 64 + mt * 16 + arow_off;
            const int colb = k16 * 32 + acol_off;
            ldsm_x4(a[mt][0], a[mt][1], a[mt][2], a[mt][3],
                    ab + swz128((uint32_t)(row * 128 + colb)));
        }
        uint32_t b[8][2];
#pragma unroll
        for (int np = 0; np < 4; np++) {
            const int row = wn * 64 + np * 16 + brow_off;
            const int colb = k16 * 32 + bcol_off;
            uint32_t r0, r1, r2, r3;
            ldsm_x4(r0, r1, r2, r3, bb + swz128((uint32_t)(row * 128 + colb)));
            b[2 * np][0] = r0; b[2 * np][1] = r1;
            b[2 * np + 1][0] = r2; b[2 * np + 1][1] = r3;
        }
#pragma unroll
        for (int mt = 0; mt < 4; mt++)
#pragma unroll
            for (int nt = 0; nt < 8; nt++)
                mma16816(acc[mt][nt], a[mt][0], a[mt][1], a[mt][2], a[mt][3],
                         b[nt][0], b[nt][1]);
    };

    for (int ks = 0; ks < KIT; ks++) {
        asm volatile("cp.async.wait_group 2;" ::: "memory");
        __syncthreads();

        const uint32_t ab = sb + SM_A + (ks % NSTG) * A_BYTES;
        const uint32_t bb = sb + SM_B + (ks % NSTG) * B_BYTES;
        const bool pf = (ks + 2 < KIT);
        const int st = (ks + 2) % NSTG;

        do_k16(ab, bb, 0);
        if (pf) load_A_half(ks + 2, st, 0);

        do_k16(ab, bb, 1);
        if (pf) load_A_half(ks + 2, st, 1);
        commit();                                  // A group (or empty)

        do_k16(ab, bb, 2);
        if (pf) load_B_half(ks + 2, st, 0);

        do_k16(ab, bb, 3);
        if (pf) load_B_half(ks + 2, st, 1);
        commit();                                  // B group (or empty)
    }

    // ---- epilogue ----
    const int crow = lane >> 2;
    const int ccol = (lane & 3) * 2;
#pragma unroll
    for (int mt = 0; mt < 4; mt++) {
        const int m = m0 + wm * 64 + mt * 16 + crow;
#pragma unroll
        for (int nt = 0; nt < 8; nt++) {
            const int nc = wn * 64 + nt * 8 + ccol;
            float2 v0, v1;
            v0.x = acc[mt][nt][0] + sbias[nc];
            v0.y = acc[mt][nt][1] + sbias[nc + 1];
            v1.x = acc[mt][nt][2] + sbias[nc];
            v1.y = acc[mt][nt][3] + sbias[nc + 1];
            *reinterpret_cast<float2*>(out + (size_t)m * SZ + n0 + nc)       = v0;
            *reinterpret_cast<float2*>(out + (size_t)(m + 8) * SZ + n0 + nc) = v1;
        }
    }
}

// ---------------------------------------------------------------------------
extern "C" void kernel_launch(void* const* d_in, const int* in_sizes, int n_in,
                              void* d_out, int out_size) {
    const float* x     = (const float*)d_in[0];
    const float* core0 = (const float*)d_in[1];
    const float* core1 = (const float*)d_in[2];
    const float* core2 = (const float*)d_in[3];
    const float* bias  = (const float*)d_in[4];
    float* out = (float*)d_out;

    static bool attr_set = false;
    if (!attr_set) {
        cudaFuncSetAttribute(k_gemm, cudaFuncAttributeMaxDynamicSharedMemorySize, SM_TOTAL);
        attr_set = true;
    }

    k_convert_x<<<(int)((size_t)MTOT * SZ / 4 / 256), 256>>>(
        reinterpret_cast<const float4*>(x));
    k_build_gt<<<dim3(16, 16), 256>>>(core0, core1, core2);
    k_gemm<<<dim3(SZ / BN, MTOT / BM), NTHR, SM_TOTAL>>>(bias, out);
}